// round 12
// baseline (speedup 1.0000x reference)
#include <cuda_runtime.h>
#include <cuda_fp16.h>
#include <cstdint>

#define SEQ   2048
#define HD    64
#define BT    128           // q rows per CTA
#define BC    64            // keys per k-tile
#define NQT   (SEQ / BT)    // 16
#define BH    32            // B*H
#define NELEM (BH * SEQ * HD)

// fp16 smem tiles: pitch 72 halves = 144 bytes per row
#define RB    144
#define TILEB 9216                    // one 64-row K or V tile
#define Q0    0                       // [128][72] half (18432 B)
#define K0    18432                   // 3-deep ring
#define V0    46080                   // 3-deep ring
#define SMEM_BYTES 73728

__device__ __align__(16) uint16_t g_Kh[NELEM];
__device__ __align__(16) uint16_t g_Vh[NELEM];

__device__ __forceinline__ uint32_t pack_f16x2(float lo, float hi) {
    uint32_t d;
    asm("cvt.rn.f16x2.f32 %0, %1, %2;" : "=r"(d) : "f"(hi), "f"(lo));
    return d;
}
__device__ __forceinline__ uint32_t smem_u32(const void* p) {
    uint32_t a;
    asm("{ .reg .u64 t; cvta.to.shared.u64 t, %1; cvt.u32.u64 %0, t; }" : "=r"(a) : "l"(p));
    return a;
}
__device__ __forceinline__ void cp16(uint32_t dst, const void* src) {
    asm volatile("cp.async.cg.shared.global [%0], [%1], 16;" :: "r"(dst), "l"(src) : "memory");
}
#define CP_COMMIT()      asm volatile("cp.async.commit_group;" ::: "memory")
#define CP_WAIT0()       asm volatile("cp.async.wait_group 0;" ::: "memory")
#define CP_WAIT_GROUP1() asm volatile("cp.async.wait_group 1;" ::: "memory")

#define LDSM_X4(r, addr) \
    asm volatile("ldmatrix.sync.aligned.m8n8.x4.shared.b16 {%0,%1,%2,%3}, [%4];" \
        : "=r"((r)[0]), "=r"((r)[1]), "=r"((r)[2]), "=r"((r)[3]) : "r"(addr))
#define LDSM_X4T(r, addr) \
    asm volatile("ldmatrix.sync.aligned.m8n8.x4.trans.shared.b16 {%0,%1,%2,%3}, [%4];" \
        : "=r"((r)[0]), "=r"((r)[1]), "=r"((r)[2]), "=r"((r)[3]) : "r"(addr))

__device__ __forceinline__ void mma_f16f32(float* c, const uint32_t* a, const uint32_t* b) {
    asm volatile(
        "mma.sync.aligned.m16n8k16.row.col.f32.f16.f16.f32 "
        "{%0,%1,%2,%3}, {%4,%5,%6,%7}, {%8,%9}, {%0,%1,%2,%3};"
        : "+f"(c[0]), "+f"(c[1]), "+f"(c[2]), "+f"(c[3])
        : "r"(a[0]), "r"(a[1]), "r"(a[2]), "r"(a[3]), "r"(b[0]), "r"(b[1]));
}
__device__ __forceinline__ void mma_f16f16(uint32_t* c, const uint32_t* a, const uint32_t* b) {
    asm volatile(
        "mma.sync.aligned.m16n8k16.row.col.f16.f16.f16.f16 "
        "{%0,%1}, {%2,%3,%4,%5}, {%6,%7}, {%0,%1};"
        : "+r"(c[0]), "+r"(c[1])
        : "r"(a[0]), "r"(a[1]), "r"(a[2]), "r"(a[3]), "r"(b[0]), "r"(b[1]));
}
__device__ __forceinline__ uint32_t h2ex2(uint32_t x) {
    uint32_t r;
    asm("ex2.approx.f16x2 %0, %1;" : "=r"(r) : "r"(x));
    return r;
}
__device__ __forceinline__ uint32_t h2_u32(__half2 h) { return *(uint32_t*)&h; }
__device__ __forceinline__ __half2 u32_h2(uint32_t u) { return *(__half2*)&u; }

// ---- pre-pass: fp32 K,V -> fp16 scratch ----
__global__ __launch_bounds__(256)
void cvt_kernel(const float* __restrict__ K, const float* __restrict__ V) {
    int i = blockIdx.x * 256 + threadIdx.x;
    float4 k = ((const float4*)K)[i];
    float4 v = ((const float4*)V)[i];
    ((uint2*)g_Kh)[i] = make_uint2(pack_f16x2(k.x, k.y), pack_f16x2(k.z, k.w));
    ((uint2*)g_Vh)[i] = make_uint2(pack_f16x2(v.x, v.y), pack_f16x2(v.z, v.w));
}

// 8 warps; warp w owns q-rows [w*16, w*16+16). S(i+1) pipelined against PV(i).
__global__ __launch_bounds__(256, 2)
void fa_mma_kernel(const float* __restrict__ Qg, float* __restrict__ Og) {
    const int qt   = NQT - 1 - blockIdx.x;           // heavy tiles first
    const int bh   = blockIdx.y;
    const int tid  = threadIdx.x;
    const int w    = tid >> 5;
    const int lane = tid & 31;
    const int g    = lane >> 2;
    const int q    = lane & 3;
    const int wr   = w * 16;

    extern __shared__ char sm[];
    const uint32_t sb = smem_u32(sm);

    const uint32_t aoff  = (uint32_t)((lane & 15) * RB + ((lane >> 4) << 4));
    const uint32_t kboff = (uint32_t)(((((lane >> 4) << 3) + (lane & 7)) * RB)
                                      + (((lane >> 3) & 1) << 4));
    const uint32_t qa = sb + Q0 + (uint32_t)(wr * RB) + aoff;

    const size_t base = (size_t)bh * SEQ * HD;
    const float*    Qb = Qg + base + (size_t)qt * BT * HD;
    const uint16_t* Kb = g_Kh + base;
    const uint16_t* Vb = g_Vh + base;
    float*          Ob = Og + base + (size_t)qt * BT * HD;

    const int last = 2 * qt + 1;                     // >= 1 always
    const float C = 1.4426950408889634f / 64.0f;     // log2(e)/64 folded into Q

    // ---- prologue: prefetch tiles 0 and 1; Q load * C -> fp16 ----
    #pragma unroll
    for (int u = 0; u < 2; u++) {
        int c = u * 256 + tid;                       // 512 chunks of 16B per tensor
        int row = c >> 3, off = (c & 7) << 4;
        cp16(sb + K0 + (uint32_t)(row * RB) + off, (const char*)Kb + row * 128 + off);
        cp16(sb + V0 + (uint32_t)(row * RB) + off, (const char*)Vb + row * 128 + off);
    }
    CP_COMMIT();
    #pragma unroll
    for (int u = 0; u < 2; u++) {
        int c = u * 256 + tid;
        int row = c >> 3, off = (c & 7) << 4;
        cp16(sb + K0 + TILEB + (uint32_t)(row * RB) + off,
             (const char*)(Kb + BC * HD) + row * 128 + off);
        cp16(sb + V0 + TILEB + (uint32_t)(row * RB) + off,
             (const char*)(Vb + BC * HD) + row * 128 + off);
    }
    CP_COMMIT();
    #pragma unroll
    for (int i = 0; i < 8; i++) {
        int idx = i * 256 + tid;                     // 2048 float4s
        int r = idx >> 4, c4 = (idx & 15) << 2;
        float4 v = *(const float4*)(Qb + r * HD + c4);
        *(uint2*)(sm + Q0 + r * RB + c4 * 2) =
            make_uint2(pack_f16x2(v.x * C, v.y * C), pack_f16x2(v.z * C, v.w * C));
    }
    CP_WAIT_GROUP1();
    __syncthreads();    // tile0 + Q ready AND visible to all threads

    // ---- S(0) ----
    uint32_t s[8][2];
    #pragma unroll
    for (int n = 0; n < 8; n++) s[n][0] = s[n][1] = 0u;
    {
        const uint32_t kb = sb + K0 + kboff;
        #pragma unroll
        for (int ks = 0; ks < 4; ks++) {
            uint32_t a[4];
            LDSM_X4(a, qa + 32 * ks);
            #pragma unroll
            for (int nn = 0; nn < 4; nn++) {
                uint32_t b[4];
                LDSM_X4(b, kb + nn * 2304 + 32 * ks);
                mma_f16f16(s[2 * nn],     a, b);
                mma_f16f16(s[2 * nn + 1], a, b + 2);
            }
        }
    }

    float o[8][4];
    float ol[4] = {0.0f, 0.0f, 0.0f, 0.0f};
    #pragma unroll
    for (int n = 0; n < 8; n++)
        #pragma unroll
        for (int j = 0; j < 4; j++) o[n][j] = 0.0f;

    const uint32_t b_ones[2] = {0x3C003C00u, 0x3C003C00u};
    const int rlo = wr + g, rhi = rlo + 8;

    for (int i = 0; i <= last; i++) {
        // Barrier A: all warps finished reads of ring slot (i+2)%3 (tile i-1)
        __syncthreads();

        if (i + 2 <= last) {  // distance-2 prefetch into ring slot (i+2)%3
            const uint32_t bo = (uint32_t)(((i + 2) % 3) * TILEB);
            const char* Kp = (const char*)(Kb + (size_t)(i + 2) * BC * HD);
            const char* Vp = (const char*)(Vb + (size_t)(i + 2) * BC * HD);
            #pragma unroll
            for (int u = 0; u < 2; u++) {
                int c = u * 256 + tid;
                int row = c >> 3, off = (c & 7) << 4;
                cp16(sb + K0 + bo + (uint32_t)(row * RB) + off, Kp + row * 128 + off);
                cp16(sb + V0 + bo + (uint32_t)(row * RB) + off, Vp + row * 128 + off);
            }
            CP_COMMIT();
            CP_WAIT_GROUP1();   // this thread's tile-(i+1) copies retired
        } else {
            CP_WAIT0();
        }
        // Barrier B: make every thread's tile-(i+1) bytes visible before LDSM
        __syncthreads();

        const bool act = !(i == last && w < 4);      // warps 0-3 dead on last tile
        if (act) {
            // ---- softmax in place: p = 2^S, mask on diagonal tiles ----
            const bool dg   = (i >= 2 * qt);
            const int shift = (2 * qt - i) * 64;     // 0 or -64
            #pragma unroll
            for (int n = 0; n < 8; n++) {
                uint32_t p0 = h2ex2(s[n][0]);   // row rlo, cols 8n+2q,+1
                uint32_t p1 = h2ex2(s[n][1]);   // row rhi
                if (dg) {
                    const int c0 = n * 8 + 2 * q;
                    __half2 colv = __floats2half2_rn((float)c0, (float)(c0 + 1));
                    __half2 m0 = __hle2(colv, __float2half2_rn((float)(rlo + shift)));
                    __half2 m1 = __hle2(colv, __float2half2_rn((float)(rhi + shift)));
                    p0 = h2_u32(__hmul2(u32_h2(p0), m0));
                    p1 = h2_u32(__hmul2(u32_h2(p1), m1));
                }
                s[n][0] = p0;
                s[n][1] = p1;
            }

            // ---- merged: PV(i) + l(i)  interleaved with  S(i+1) ----
            const bool nx = (i < last);
            const uint32_t vb = sb + V0 + (uint32_t)((i % 3) * TILEB) + aoff;
            const uint32_t kb = sb + K0 + (uint32_t)(((i + 1) % 3) * TILEB) + kboff;
            uint32_t snx[8][2];
            #pragma unroll
            for (int n = 0; n < 8; n++) snx[n][0] = snx[n][1] = 0u;

            #pragma unroll
            for (int ks = 0; ks < 4; ks++) {
                uint32_t a[4] = { s[2 * ks][0], s[2 * ks][1],
                                  s[2 * ks + 1][0], s[2 * ks + 1][1] };   // P A-frag = S C-frag
                mma_f16f32(ol, a, b_ones);
                uint32_t aq[4];
                if (nx) LDSM_X4(aq, qa + 32 * ks);
                #pragma unroll
                for (int nn = 0; nn < 4; nn++) {
                    uint32_t bv[4];
                    LDSM_X4T(bv, vb + ks * 2304 + nn * 32);
                    mma_f16f32(o[2 * nn],     a, bv);
                    mma_f16f32(o[2 * nn + 1], a, bv + 2);
                    if (nx) {
                        uint32_t bk[4];
                        LDSM_X4(bk, kb + nn * 2304 + 32 * ks);
                        mma_f16f16(snx[2 * nn],     aq, bk);
                        mma_f16f16(snx[2 * nn + 1], aq, bk + 2);
                    }
                }
            }
            if (nx) {
                #pragma unroll
                for (int n = 0; n < 8; n++) { s[n][0] = snx[n][0]; s[n][1] = snx[n][1]; }
            }
        }
    }

    __syncthreads();        // all smem reads done; reuse for staging
    // ---- epilogue: normalize (l from ones-MMA: c[0]=row lo, c[2]=row hi) ----
    float* Of = (float*)sm;
    {
        const float invlo = 1.0f / ol[0];
        const float invhi = 1.0f / ol[2];
        #pragma unroll
        for (int n = 0; n < 8; n++) {
            const int c0 = n * 8 + 2 * q;
            *(float2*)(Of + rlo * 68 + c0) = make_float2(o[n][0] * invlo, o[n][1] * invlo);
            *(float2*)(Of + rhi * 68 + c0) = make_float2(o[n][2] * invhi, o[n][3] * invhi);
        }
    }
    __syncthreads();
    #pragma unroll
    for (int i = 0; i < 8; i++) {
        int idx = i * 256 + tid;
        int r = idx >> 4, c4 = (idx & 15) << 2;
        float4 v = *(const float4*)(Of + r * 68 + c4);
        *(float4*)(Ob + r * HD + c4) = v;
    }
}

extern "C" void kernel_launch(void* const* d_in, const int* in_sizes, int n_in,
                              void* d_out, int out_size) {
    const float* Q = (const float*)d_in[0];
    const float* K = (const float*)d_in[1];
    const float* V = (const float*)d_in[2];
    float* O = (float*)d_out;

    cvt_kernel<<<NELEM / 4 / 256, 256>>>(K, V);

    cudaFuncSetAttribute(fa_mma_kernel,
                         cudaFuncAttributeMaxDynamicSharedMemorySize, SMEM_BYTES);
    dim3 grid(NQT, BH);
    fa_mma_kernel<<<grid, 256, SMEM_BYTES>>>(Q, O);
}

// round 13
// speedup vs baseline: 1.3142x; 1.3142x over previous
#include <cuda_runtime.h>
#include <cuda_fp16.h>
#include <cstdint>

#define SEQ   2048
#define HD    64
#define BT    64            // q rows per CTA
#define BC    64            // keys per k-tile
#define NQT   (SEQ / BT)    // 32
#define BH    32            // B*H
#define NELEM (BH * SEQ * HD)

// fp16 smem tiles: pitch 72 halves = 144 bytes per row
#define RB    144
#define TILEB 9216                    // one 64-row K or V tile
#define Q0    0                       // [64][72] half (9216 B)
#define K0    9216                    // 2-deep K ring (K(i) dies after iter i-1)
#define V0    27648                   // 3-deep V ring
#define SMEM_BYTES 55296

__device__ __align__(16) uint16_t g_Kh[NELEM];
__device__ __align__(16) uint16_t g_Vh[NELEM];

__device__ __forceinline__ uint32_t pack_f16x2(float lo, float hi) {
    uint32_t d;
    asm("cvt.rn.f16x2.f32 %0, %1, %2;" : "=r"(d) : "f"(hi), "f"(lo));
    return d;
}
__device__ __forceinline__ uint32_t smem_u32(const void* p) {
    uint32_t a;
    asm("{ .reg .u64 t; cvta.to.shared.u64 t, %1; cvt.u32.u64 %0, t; }" : "=r"(a) : "l"(p));
    return a;
}
__device__ __forceinline__ void cp16(uint32_t dst, const void* src) {
    asm volatile("cp.async.cg.shared.global [%0], [%1], 16;" :: "r"(dst), "l"(src) : "memory");
}
#define CP_COMMIT()      asm volatile("cp.async.commit_group;" ::: "memory")
#define CP_WAIT0()       asm volatile("cp.async.wait_group 0;" ::: "memory")
#define CP_WAIT_GROUP1() asm volatile("cp.async.wait_group 1;" ::: "memory")

#define LDSM_X4(r, addr) \
    asm volatile("ldmatrix.sync.aligned.m8n8.x4.shared.b16 {%0,%1,%2,%3}, [%4];" \
        : "=r"((r)[0]), "=r"((r)[1]), "=r"((r)[2]), "=r"((r)[3]) : "r"(addr))
#define LDSM_X4T(r, addr) \
    asm volatile("ldmatrix.sync.aligned.m8n8.x4.trans.shared.b16 {%0,%1,%2,%3}, [%4];" \
        : "=r"((r)[0]), "=r"((r)[1]), "=r"((r)[2]), "=r"((r)[3]) : "r"(addr))

__device__ __forceinline__ void mma_f16f32(float* c, const uint32_t* a, const uint32_t* b) {
    asm volatile(
        "mma.sync.aligned.m16n8k16.row.col.f32.f16.f16.f32 "
        "{%0,%1,%2,%3}, {%4,%5,%6,%7}, {%8,%9}, {%0,%1,%2,%3};"
        : "+f"(c[0]), "+f"(c[1]), "+f"(c[2]), "+f"(c[3])
        : "r"(a[0]), "r"(a[1]), "r"(a[2]), "r"(a[3]), "r"(b[0]), "r"(b[1]));
}
__device__ __forceinline__ void mma_f16f16(uint32_t* c, const uint32_t* a, const uint32_t* b) {
    asm volatile(
        "mma.sync.aligned.m16n8k16.row.col.f16.f16.f16.f16 "
        "{%0,%1}, {%2,%3,%4,%5}, {%6,%7}, {%0,%1};"
        : "+r"(c[0]), "+r"(c[1])
        : "r"(a[0]), "r"(a[1]), "r"(a[2]), "r"(a[3]), "r"(b[0]), "r"(b[1]));
}
__device__ __forceinline__ uint32_t h2ex2(uint32_t x) {
    uint32_t r;
    asm("ex2.approx.f16x2 %0, %1;" : "=r"(r) : "r"(x));
    return r;
}
__device__ __forceinline__ uint32_t h2_u32(__half2 h) { return *(uint32_t*)&h; }
__device__ __forceinline__ __half2 u32_h2(uint32_t u) { return *(__half2*)&u; }

// ---- pre-pass: fp32 K,V -> fp16 scratch ----
__global__ __launch_bounds__(256)
void cvt_kernel(const float* __restrict__ K, const float* __restrict__ V) {
    int i = blockIdx.x * 256 + threadIdx.x;
    float4 k = ((const float4*)K)[i];
    float4 v = ((const float4*)V)[i];
    ((uint2*)g_Kh)[i] = make_uint2(pack_f16x2(k.x, k.y), pack_f16x2(k.z, k.w));
    ((uint2*)g_Vh)[i] = make_uint2(pack_f16x2(v.x, v.y), pack_f16x2(v.z, v.w));
}

// 4 warps; warp w owns q-rows [w*16, w*16+16). S(i+1) pipelined against PV(i).
__global__ __launch_bounds__(128, 4)
void fa_mma_kernel(const float* __restrict__ Qg, float* __restrict__ Og) {
    const int qt   = NQT - 1 - blockIdx.x;           // heavy tiles first
    const int bh   = blockIdx.y;
    const int tid  = threadIdx.x;
    const int w    = tid >> 5;
    const int lane = tid & 31;
    const int g    = lane >> 2;
    const int q    = lane & 3;
    const int wr   = w * 16;

    extern __shared__ char sm[];
    const uint32_t sb = smem_u32(sm);

    const uint32_t aoff  = (uint32_t)((lane & 15) * RB + ((lane >> 4) << 4));
    const uint32_t kboff = (uint32_t)(((((lane >> 4) << 3) + (lane & 7)) * RB)
                                      + (((lane >> 3) & 1) << 4));
    const uint32_t qa = sb + Q0 + (uint32_t)(wr * RB) + aoff;

    const size_t base = (size_t)bh * SEQ * HD;
    const float*    Qb = Qg + base + (size_t)qt * BT * HD;
    const uint16_t* Kb = g_Kh + base;
    const uint16_t* Vb = g_Vh + base;
    float*          Ob = Og + base + (size_t)qt * BT * HD;

    const float C = 1.4426950408889634f / 64.0f;     // log2(e)/64 folded into Q

    // ---- prologue: prefetch tiles 0 (and 1); Q load * C -> fp16 ----
    #pragma unroll
    for (int u = 0; u < 4; u++) {
        int c = u * 128 + tid;
        int row = c >> 3, off = (c & 7) << 4;
        cp16(sb + K0 + (uint32_t)(row * RB) + off, (const char*)Kb + row * 128 + off);
        cp16(sb + V0 + (uint32_t)(row * RB) + off, (const char*)Vb + row * 128 + off);
    }
    CP_COMMIT();
    if (qt >= 1) {
        #pragma unroll
        for (int u = 0; u < 4; u++) {
            int c = u * 128 + tid;
            int row = c >> 3, off = (c & 7) << 4;
            cp16(sb + K0 + TILEB + (uint32_t)(row * RB) + off,
                 (const char*)(Kb + BC * HD) + row * 128 + off);
            cp16(sb + V0 + TILEB + (uint32_t)(row * RB) + off,
                 (const char*)(Vb + BC * HD) + row * 128 + off);
        }
        CP_COMMIT();
    }
    #pragma unroll
    for (int i = 0; i < 8; i++) {
        int idx = i * 128 + tid;                     // 1024 float4s
        int r = idx >> 4, c4 = (idx & 15) << 2;
        float4 v = *(const float4*)(Qb + r * HD + c4);
        *(uint2*)(sm + Q0 + r * RB + c4 * 2) =
            make_uint2(pack_f16x2(v.x * C, v.y * C), pack_f16x2(v.z * C, v.w * C));
    }
    if (qt >= 1) { CP_WAIT_GROUP1(); } else { CP_WAIT0(); }
    __syncthreads();    // tile0 + Q ready AND visible to all threads

    // ---- S(0)  (K tile 0 in K-slot 0) ----
    uint32_t s[8][2];
    #pragma unroll
    for (int n = 0; n < 8; n++) s[n][0] = s[n][1] = 0u;
    {
        const uint32_t kb = sb + K0 + kboff;
        #pragma unroll
        for (int ks = 0; ks < 4; ks++) {
            uint32_t a[4];
            LDSM_X4(a, qa + 32 * ks);
            #pragma unroll
            for (int nn = 0; nn < 4; nn++) {
                uint32_t b[4];
                LDSM_X4(b, kb + nn * 2304 + 32 * ks);
                mma_f16f16(s[2 * nn],     a, b);
                mma_f16f16(s[2 * nn + 1], a, b + 2);
            }
        }
    }

    float o[8][4];
    float ol[4] = {0.0f, 0.0f, 0.0f, 0.0f};
    #pragma unroll
    for (int n = 0; n < 8; n++)
        #pragma unroll
        for (int j = 0; j < 4; j++) o[n][j] = 0.0f;

    const uint32_t b_ones[2] = {0x3C003C00u, 0x3C003C00u};
    const int rlo = wr + g, rhi = rlo + 8;

    for (int i = 0; i <= qt; i++) {
        // Barrier A: all warps finished iteration i-1's reads (K slot i%2 =
        // K(i) dead since S(i) done; V slot (i+2)%3 = V(i-1) dead).
        __syncthreads();

        if (i + 2 <= qt) {  // distance-2 prefetch: K(i+2)->slot (i+2)%2, V(i+2)->slot (i+2)%3
            const uint32_t bok = (uint32_t)(((i + 2) & 1) * TILEB);
            const uint32_t bov = (uint32_t)(((i + 2) % 3) * TILEB);
            const char* Kp = (const char*)(Kb + (size_t)(i + 2) * BC * HD);
            const char* Vp = (const char*)(Vb + (size_t)(i + 2) * BC * HD);
            #pragma unroll
            for (int u = 0; u < 4; u++) {
                int c = u * 128 + tid;
                int row = c >> 3, off = (c & 7) << 4;
                cp16(sb + K0 + bok + (uint32_t)(row * RB) + off, Kp + row * 128 + off);
                cp16(sb + V0 + bov + (uint32_t)(row * RB) + off, Vp + row * 128 + off);
            }
            CP_COMMIT();
            CP_WAIT_GROUP1();   // this thread's tile-(i+1) copies retired
        } else {
            CP_WAIT0();
        }
        // Barrier B: make every thread's tile-(i+1) bytes visible before LDSM
        __syncthreads();

        // ---- softmax in place: p = 2^S, mask on diagonal tile ----
        const bool dg = (i == qt);
        #pragma unroll
        for (int n = 0; n < 8; n++) {
            uint32_t p0 = h2ex2(s[n][0]);   // row rlo, cols 8n+2q,+1
            uint32_t p1 = h2ex2(s[n][1]);   // row rhi
            if (dg) {
                const int c0 = n * 8 + 2 * q;
                __half2 colv = __floats2half2_rn((float)c0, (float)(c0 + 1));
                __half2 m0 = __hle2(colv, __float2half2_rn((float)rlo));
                __half2 m1 = __hle2(colv, __float2half2_rn((float)rhi));
                p0 = h2_u32(__hmul2(u32_h2(p0), m0));
                p1 = h2_u32(__hmul2(u32_h2(p1), m1));
            }
            s[n][0] = p0;
            s[n][1] = p1;
        }

        // ---- merged: PV(i) + l(i)  interleaved with  S(i+1) ----
        const bool nx = (i < qt);
        const uint32_t vb = sb + V0 + (uint32_t)((i % 3) * TILEB) + aoff;
        const uint32_t kb = sb + K0 + (uint32_t)(((i + 1) & 1) * TILEB) + kboff;
        uint32_t snx[8][2];
        #pragma unroll
        for (int n = 0; n < 8; n++) snx[n][0] = snx[n][1] = 0u;

        #pragma unroll
        for (int ks = 0; ks < 4; ks++) {
            uint32_t a[4] = { s[2 * ks][0], s[2 * ks][1],
                              s[2 * ks + 1][0], s[2 * ks + 1][1] };   // P A-frag = S C-frag
            mma_f16f32(ol, a, b_ones);
            uint32_t aq[4];
            if (nx) LDSM_X4(aq, qa + 32 * ks);
            #pragma unroll
            for (int nn = 0; nn < 4; nn++) {
                uint32_t bv[4];
                LDSM_X4T(bv, vb + ks * 2304 + nn * 32);
                mma_f16f32(o[2 * nn],     a, bv);
                mma_f16f32(o[2 * nn + 1], a, bv + 2);
                if (nx) {
                    uint32_t bk[4];
                    LDSM_X4(bk, kb + nn * 2304 + 32 * ks);
                    mma_f16f16(snx[2 * nn],     aq, bk);
                    mma_f16f16(snx[2 * nn + 1], aq, bk + 2);
                }
            }
        }
        if (nx) {
            #pragma unroll
            for (int n = 0; n < 8; n++) { s[n][0] = snx[n][0]; s[n][1] = snx[n][1]; }
        }
    }

    __syncthreads();        // all smem reads done; reuse for staging
    // ---- epilogue: normalize (l from ones-MMA: c[0]=row lo, c[2]=row hi) ----
    float* Of = (float*)sm;
    {
        const float invlo = 1.0f / ol[0];
        const float invhi = 1.0f / ol[2];
        #pragma unroll
        for (int n = 0; n < 8; n++) {
            const int c0 = n * 8 + 2 * q;
            *(float2*)(Of + rlo * 68 + c0) = make_float2(o[n][0] * invlo, o[n][1] * invlo);
            *(float2*)(Of + rhi * 68 + c0) = make_float2(o[n][2] * invhi, o[n][3] * invhi);
        }
    }
    __syncthreads();
    #pragma unroll
    for (int i = 0; i < 8; i++) {
        int idx = i * 128 + tid;
        int r = idx >> 4, c4 = (idx & 15) << 2;
        float4 v = *(const float4*)(Of + r * 68 + c4);
        *(float4*)(Ob + r * HD + c4) = v;
    }
}

extern "C" void kernel_launch(void* const* d_in, const int* in_sizes, int n_in,
                              void* d_out, int out_size) {
    const float* Q = (const float*)d_in[0];
    const float* K = (const float*)d_in[1];
    const float* V = (const float*)d_in[2];
    float* O = (float*)d_out;

    cvt_kernel<<<NELEM / 4 / 256, 256>>>(K, V);

    cudaFuncSetAttribute(fa_mma_kernel,
                         cudaFuncAttributeMaxDynamicSharedMemorySize, SMEM_BYTES);
    dim3 grid(NQT, BH);
    fa_mma_kernel<<<grid, 128, SMEM_BYTES>>>(Q, O);
}